// round 1
// baseline (speedup 1.0000x reference)
#include <cuda_runtime.h>

// ---------------------------------------------------------------------------
// DGCNN segmentation, fp32.
//
// EdgeConv decomposition:  m = relu([x_i, x_j - x_i] @ W1 + b1) @ W2 + b2
//   [x_i, x_j-x_i] @ W1 = x_i @ (W1_top - W1_bot) + x_j @ W1_bot
// => per-node precompute AB = [A | B],  A = x@(Wt-Wb)+b1,  B = x@Wb
// => per-edge hidden h = relu(A[dst] + B[src]); m = h @ W2 + b2
// => segment max via ordered-uint atomicMax into agg, decoded into hcat.
// ---------------------------------------------------------------------------

#define NMAX 30016
#define EMAX 480256

__device__ float    g_AB[NMAX * 512];     // node precompute [N, 2H], H<=256
__device__ unsigned g_agg[NMAX * 256];    // segment-max accumulator (ordered uint)
__device__ float    g_hcat[NMAX * 448];   // [h1 | h2 | h3]
__device__ float    g_m1[NMAX * 512];
__device__ float    g_m2[NMAX * 256];
__device__ float    g_wc1[3 * 128];
__device__ float    g_wc2[64 * 256];
__device__ float    g_wc3[128 * 512];
__device__ float    g_bc1[128];
__device__ float    g_bc2[256];
__device__ float    g_bc3[512];
__device__ int      g_src[EMAX];
__device__ int      g_dst[EMAX];
__device__ int      g_is64;

// ---- ordered-uint encoding for float max (monotonic, NaN-free inputs) ------
__device__ __forceinline__ unsigned f2ord(float f) {
    int i = __float_as_int(f);
    return (i >= 0) ? ((unsigned)i | 0x80000000u) : ~(unsigned)i;
}
__device__ __forceinline__ float ord2f(unsigned u) {
    int i = (u & 0x80000000u) ? (int)(u & 0x7fffffffu) : (int)(~u);
    return __int_as_float(i);
}

// ---- edge_index dtype detection (int64 vs silently-downgraded int32) -------
__global__ void detect_idx_kernel(const unsigned* __restrict__ p, int E) {
    if (threadIdx.x == 0 && blockIdx.x == 0) {
        int n = (E < 256) ? E : 256;
        int is64 = 1;
        for (int i = 0; i < n; i++) {
            if (p[2 * i + 1] != 0u) { is64 = 0; break; }  // high word of int64 idx is 0
        }
        g_is64 = is64;
    }
}

__global__ void convert_idx_kernel(const void* __restrict__ raw, int E) {
    int i = blockIdx.x * blockDim.x + threadIdx.x;
    if (i >= E) return;
    if (g_is64) {
        const long long* p = (const long long*)raw;
        g_src[i] = (int)p[i];
        g_dst[i] = (int)p[E + i];
    } else {
        const int* p = (const int*)raw;
        g_src[i] = p[i];
        g_dst[i] = p[E + i];
    }
}

// ---- weight prep: wc = [Wtop - Wbot | Wbot], bc = [b | 0] ------------------
__global__ void prep_kernel(const float* __restrict__ w, const float* __restrict__ b,
                            float* __restrict__ wc, float* __restrict__ bc,
                            int C, int H) {
    int stride = gridDim.x * blockDim.x;
    int i0 = blockIdx.x * blockDim.x + threadIdx.x;
    for (int t = i0; t < C * H; t += stride) {
        int k = t / H, j = t % H;
        float wd = w[(k + C) * H + j];
        wc[k * 2 * H + j]     = w[k * H + j] - wd;
        wc[k * 2 * H + H + j] = wd;
    }
    for (int t = i0; t < H; t += stride) {
        bc[t]     = b[t];
        bc[H + t] = 0.f;
    }
}

// ---- layer-1 node precompute: K=3, out width 128 ---------------------------
__global__ void node1_kernel(const float* __restrict__ x,
                             const float* __restrict__ wc,
                             const float* __restrict__ bc,
                             float* __restrict__ AB, int M) {
    int idx = blockIdx.x * blockDim.x + threadIdx.x;
    if (idx >= M * 128) return;
    int n = idx >> 7, j = idx & 127;
    float x0 = x[n * 3 + 0], x1 = x[n * 3 + 1], x2 = x[n * 3 + 2];
    AB[idx] = fmaf(x0, wc[j], fmaf(x1, wc[128 + j], fmaf(x2, wc[256 + j], bc[j])));
}

// ---- generic tiled SGEMM: C = act(A[M,K](lda) @ W[K,N](ldw) + bias) --------
// Requires K%16==0, N%128==0, 16B-aligned A/W, lda%4==0. M guarded.
template <bool RELU>
__global__ void __launch_bounds__(256, 2)
sgemm_bias_kernel(const float* __restrict__ A, int lda,
                  const float* __restrict__ W, int ldw,
                  const float* __restrict__ bias,
                  float* __restrict__ C, int ldc,
                  int M, int N, int K) {
    constexpr int BM = 128, BN = 128, BK = 16;
    __shared__ float As[BK][BM + 4];
    __shared__ float Ws[BK][BN];
    const int tid = threadIdx.x;
    const int bm = blockIdx.x * BM;
    const int bn = blockIdx.y * BN;
    const int rowb = (tid / 16) * 8;
    const int colb = (tid % 16) * 8;
    const int a_m = tid >> 2;
    const int a_k = (tid & 3) * 4;
    const int w_r = tid >> 4;
    const int w_c = (tid & 15) * 8;

    float acc[8][8];
#pragma unroll
    for (int i = 0; i < 8; i++)
#pragma unroll
        for (int j = 0; j < 8; j++) acc[i][j] = 0.f;

    for (int k0 = 0; k0 < K; k0 += BK) {
#pragma unroll
        for (int p = 0; p < 2; p++) {
            int m = a_m + p * 64;
            float4 v = make_float4(0.f, 0.f, 0.f, 0.f);
            if (bm + m < M)
                v = *reinterpret_cast<const float4*>(A + (size_t)(bm + m) * lda + k0 + a_k);
            As[a_k + 0][m] = v.x;
            As[a_k + 1][m] = v.y;
            As[a_k + 2][m] = v.z;
            As[a_k + 3][m] = v.w;
        }
#pragma unroll
        for (int q = 0; q < 2; q++) {
            *reinterpret_cast<float4*>(&Ws[w_r][w_c + q * 4]) =
                *reinterpret_cast<const float4*>(W + (size_t)(k0 + w_r) * ldw + bn + w_c + q * 4);
        }
        __syncthreads();
#pragma unroll
        for (int kk = 0; kk < BK; kk++) {
            float af[8], wf[8];
#pragma unroll
            for (int i = 0; i < 8; i++) af[i] = As[kk][rowb + i];
#pragma unroll
            for (int j = 0; j < 8; j++) wf[j] = Ws[kk][colb + j];
#pragma unroll
            for (int i = 0; i < 8; i++)
#pragma unroll
                for (int j = 0; j < 8; j++) acc[i][j] = fmaf(af[i], wf[j], acc[i][j]);
        }
        __syncthreads();
    }

#pragma unroll
    for (int i = 0; i < 8; i++) {
        int m = bm + rowb + i;
        if (m >= M) break;
#pragma unroll
        for (int j = 0; j < 8; j++) {
            float v = acc[i][j] + bias[bn + colb + j];
            if (RELU) v = fmaxf(v, 0.f);
            C[(size_t)m * ldc + bn + colb + j] = v;
        }
    }
}

// ---- fused edge kernel: h = relu(A[dst]+B[src]); m = h@W2+b2; atomicMax ----
template <int H, int COUT, int BN>
__global__ void __launch_bounds__(256, 2)
edge_conv_kernel(const float* __restrict__ AB,
                 const float* __restrict__ W2,   // [H, COUT] row-major
                 const float* __restrict__ b2,
                 unsigned* __restrict__ agg,     // [N, COUT]
                 int E) {
    constexpr int BM = 128, BK = 16;
    constexpr int CN = BN / 16;
    __shared__ float Hs[BK][BM + 4];
    __shared__ float Ws[BK][BN];
    __shared__ int ssrc[BM];
    __shared__ int sdst[BM];

    const int tid = threadIdx.x;
    const int e0 = blockIdx.x * BM;
    const int bn = blockIdx.y * BN;

    if (tid < BM) {
        int e = e0 + tid;
        ssrc[tid] = (e < E) ? g_src[e] : 0;
    } else {
        int e = e0 + tid - BM;
        sdst[tid - BM] = (e < E) ? g_dst[e] : 0;
    }
    __syncthreads();

    const int rowb = (tid / 16) * 8;
    const int colb = (tid % 16) * CN;
    const int g_m = tid >> 1;
    const int g_h = (tid & 1) * 8;
    const int w_r = tid >> 4;
    const int w_c = (tid & 15) * CN;

    float acc[8][CN];
#pragma unroll
    for (int i = 0; i < 8; i++)
#pragma unroll
        for (int j = 0; j < CN; j++) acc[i][j] = 0.f;

    const float* Abase = AB + (size_t)sdst[g_m] * (2 * H) + g_h;
    const float* Bbase = AB + (size_t)ssrc[g_m] * (2 * H) + H + g_h;

    for (int k0 = 0; k0 < H; k0 += BK) {
        float4 a0 = *reinterpret_cast<const float4*>(Abase + k0);
        float4 a1 = *reinterpret_cast<const float4*>(Abase + k0 + 4);
        float4 c0 = *reinterpret_cast<const float4*>(Bbase + k0);
        float4 c1 = *reinterpret_cast<const float4*>(Bbase + k0 + 4);
        Hs[g_h + 0][g_m] = fmaxf(a0.x + c0.x, 0.f);
        Hs[g_h + 1][g_m] = fmaxf(a0.y + c0.y, 0.f);
        Hs[g_h + 2][g_m] = fmaxf(a0.z + c0.z, 0.f);
        Hs[g_h + 3][g_m] = fmaxf(a0.w + c0.w, 0.f);
        Hs[g_h + 4][g_m] = fmaxf(a1.x + c1.x, 0.f);
        Hs[g_h + 5][g_m] = fmaxf(a1.y + c1.y, 0.f);
        Hs[g_h + 6][g_m] = fmaxf(a1.z + c1.z, 0.f);
        Hs[g_h + 7][g_m] = fmaxf(a1.w + c1.w, 0.f);
#pragma unroll
        for (int q = 0; q < CN / 4; q++) {
            *reinterpret_cast<float4*>(&Ws[w_r][w_c + q * 4]) =
                *reinterpret_cast<const float4*>(W2 + (size_t)(k0 + w_r) * COUT + bn + w_c + q * 4);
        }
        __syncthreads();
#pragma unroll
        for (int kk = 0; kk < BK; kk++) {
            float af[8], wf[CN];
#pragma unroll
            for (int i = 0; i < 8; i++) af[i] = Hs[kk][rowb + i];
#pragma unroll
            for (int j = 0; j < CN; j++) wf[j] = Ws[kk][colb + j];
#pragma unroll
            for (int i = 0; i < 8; i++)
#pragma unroll
                for (int j = 0; j < CN; j++) acc[i][j] = fmaf(af[i], wf[j], acc[i][j]);
        }
        __syncthreads();
    }

#pragma unroll
    for (int i = 0; i < 8; i++) {
        int e = rowb + i;
        if (e0 + e >= E) break;
        unsigned* arow = agg + (size_t)sdst[e] * COUT + bn + colb;
#pragma unroll
        for (int j = 0; j < CN; j++) {
            float v = acc[i][j] + b2[bn + colb + j];
            unsigned key = f2ord(v);
            // stale read is only ever <= current (monotonic) -> skip is safe
            if (key > arow[j]) atomicMax(arow + j, key);
        }
    }
}

// ---- decode agg -> float, empty segments (sentinel 0u) -> 0 ---------------
__global__ void decode_kernel(const unsigned* __restrict__ agg,
                              float* __restrict__ dsth, int total, int C, int ldc) {
    int i = blockIdx.x * blockDim.x + threadIdx.x;
    if (i >= total) return;
    int n = i / C, c = i % C;
    unsigned u = agg[i];
    dsth[(size_t)n * ldc + c] = (u == 0u) ? 0.f : ord2f(u);
}

__global__ void clear_kernel(unsigned* __restrict__ p, int n) {
    int i = blockIdx.x * blockDim.x + threadIdx.x;
    if (i < n) p[i] = 0u;
}

// ---- final 256 -> 4 linear: one warp per node ------------------------------
__global__ void mlp3_kernel(const float* __restrict__ A, const float* __restrict__ W,
                            const float* __restrict__ b, float* __restrict__ out, int M) {
    int gw = (blockIdx.x * blockDim.x + threadIdx.x) >> 5;
    int lane = threadIdx.x & 31;
    if (gw >= M) return;
    const float* a = A + (size_t)gw * 256;
    float acc0 = 0.f, acc1 = 0.f, acc2 = 0.f, acc3 = 0.f;
    for (int k = lane; k < 256; k += 32) {
        float av = a[k];
        const float* wr = W + k * 4;
        acc0 = fmaf(av, wr[0], acc0);
        acc1 = fmaf(av, wr[1], acc1);
        acc2 = fmaf(av, wr[2], acc2);
        acc3 = fmaf(av, wr[3], acc3);
    }
#pragma unroll
    for (int off = 16; off > 0; off >>= 1) {
        acc0 += __shfl_down_sync(0xffffffffu, acc0, off);
        acc1 += __shfl_down_sync(0xffffffffu, acc1, off);
        acc2 += __shfl_down_sync(0xffffffffu, acc2, off);
        acc3 += __shfl_down_sync(0xffffffffu, acc3, off);
    }
    if (lane == 0) {
        out[gw * 4 + 0] = acc0 + b[0];
        out[gw * 4 + 1] = acc1 + b[1];
        out[gw * 4 + 2] = acc2 + b[2];
        out[gw * 4 + 3] = acc3 + b[3];
    }
}

// ---------------------------------------------------------------------------
extern "C" void kernel_launch(void* const* d_in, const int* in_sizes, int n_in,
                              void* d_out, int out_size) {
    const float* x   = (const float*)d_in[0];
    const void*  ei  = d_in[1];
    const float* w1a = (const float*)d_in[3];
    const float* b1a = (const float*)d_in[4];
    const float* w1b = (const float*)d_in[5];
    const float* b1b = (const float*)d_in[6];
    const float* w2a = (const float*)d_in[7];
    const float* b2a = (const float*)d_in[8];
    const float* w2b = (const float*)d_in[9];
    const float* b2b = (const float*)d_in[10];
    const float* w3a = (const float*)d_in[11];
    const float* b3a = (const float*)d_in[12];
    const float* w3b = (const float*)d_in[13];
    const float* b3b = (const float*)d_in[14];
    const float* wm1 = (const float*)d_in[15];
    const float* bm1 = (const float*)d_in[16];
    const float* wm2 = (const float*)d_in[17];
    const float* bm2 = (const float*)d_in[18];
    const float* wm3 = (const float*)d_in[19];
    const float* bm3 = (const float*)d_in[20];

    const int Nn = in_sizes[0] / 3;
    const int E  = in_sizes[1] / 2;
    float* out = (float*)d_out;

    float *AB, *hcat, *m1, *m2, *wc1, *wc2, *wc3, *bc1, *bc2, *bc3;
    unsigned* agg;
    cudaGetSymbolAddress((void**)&AB,   g_AB);
    cudaGetSymbolAddress((void**)&agg,  g_agg);
    cudaGetSymbolAddress((void**)&hcat, g_hcat);
    cudaGetSymbolAddress((void**)&m1,   g_m1);
    cudaGetSymbolAddress((void**)&m2,   g_m2);
    cudaGetSymbolAddress((void**)&wc1,  g_wc1);
    cudaGetSymbolAddress((void**)&wc2,  g_wc2);
    cudaGetSymbolAddress((void**)&wc3,  g_wc3);
    cudaGetSymbolAddress((void**)&bc1,  g_bc1);
    cudaGetSymbolAddress((void**)&bc2,  g_bc2);
    cudaGetSymbolAddress((void**)&bc3,  g_bc3);

    const int TB = 256;
    dim3 blk(TB);

    // edge index normalization
    detect_idx_kernel<<<1, 32>>>((const unsigned*)ei, E);
    convert_idx_kernel<<<(E + TB - 1) / TB, blk>>>(ei, E);

    // weight prep
    prep_kernel<<<(3 * 64 + TB - 1) / TB, blk>>>(w1a, b1a, wc1, bc1, 3, 64);
    prep_kernel<<<(64 * 128 + TB - 1) / TB, blk>>>(w2a, b2a, wc2, bc2, 64, 128);
    prep_kernel<<<(128 * 256 + TB - 1) / TB, blk>>>(w3a, b3a, wc3, bc3, 128, 256);

    const int gx = (Nn + 127) / 128;
    const int egx = (E + 127) / 128;

    // ---- EdgeConv 1: 3 -> 64 ----
    node1_kernel<<<(Nn * 128 + TB - 1) / TB, blk>>>(x, wc1, bc1, AB, Nn);
    clear_kernel<<<(Nn * 64 + TB - 1) / TB, blk>>>(agg, Nn * 64);
    edge_conv_kernel<64, 64, 64><<<dim3(egx, 1), blk>>>(AB, w1b, b1b, agg, E);
    decode_kernel<<<(Nn * 64 + TB - 1) / TB, blk>>>(agg, hcat + 0, Nn * 64, 64, 448);

    // ---- EdgeConv 2: 64 -> 128 ----
    sgemm_bias_kernel<false><<<dim3(gx, 2), blk>>>(hcat, 448, wc2, 256, bc2, AB, 256, Nn, 256, 64);
    clear_kernel<<<(Nn * 128 + TB - 1) / TB, blk>>>(agg, Nn * 128);
    edge_conv_kernel<128, 128, 128><<<dim3(egx, 1), blk>>>(AB, w2b, b2b, agg, E);
    decode_kernel<<<(Nn * 128 + TB - 1) / TB, blk>>>(agg, hcat + 64, Nn * 128, 128, 448);

    // ---- EdgeConv 3: 128 -> 256 ----
    sgemm_bias_kernel<false><<<dim3(gx, 4), blk>>>(hcat + 64, 448, wc3, 512, bc3, AB, 512, Nn, 512, 128);
    clear_kernel<<<(Nn * 256 + TB - 1) / TB, blk>>>(agg, Nn * 256);
    edge_conv_kernel<256, 256, 128><<<dim3(egx, 2), blk>>>(AB, w3b, b3b, agg, E);
    decode_kernel<<<(Nn * 256 + TB - 1) / TB, blk>>>(agg, hcat + 192, Nn * 256, 256, 448);

    // ---- MLP head ----
    sgemm_bias_kernel<true><<<dim3(gx, 4), blk>>>(hcat, 448, wm1, 512, bm1, m1, 512, Nn, 512, 448);
    sgemm_bias_kernel<true><<<dim3(gx, 2), blk>>>(m1, 512, wm2, 256, bm2, m2, 256, Nn, 256, 512);
    mlp3_kernel<<<(Nn * 32 + TB - 1) / TB, blk>>>(m2, wm3, bm3, out, Nn);
}